// round 4
// baseline (speedup 1.0000x reference)
#include <cuda_runtime.h>

#define TOK   4608      // n*H*W
#define NB    2
#define HH    48
#define WW    48
#define DM    256
#define NHEAD 4
#define EH    64
#define EPS   1e-6f

// ---------------- scratch ----------------
__device__ float g_scale[NB * DM];
__device__ float g_xn  [TOK * DM];
__device__ float g_q   [NB * NHEAD * HH * WW * EH];
__device__ float g_k   [NB * NHEAD * HH * WW * EH];
__device__ float g_v   [NB * NHEAD * HH * WW * EH];
__device__ float g_o   [TOK * DM];

// ---------------- packed f32x2 helpers ----------------
__device__ __forceinline__ unsigned long long dupf(float x) {
    unsigned long long r;
    asm("mov.b64 %0,{%1,%2};" : "=l"(r) : "f"(x), "f"(x));
    return r;
}
__device__ __forceinline__ void ffma2(unsigned long long& c, unsigned long long a, unsigned long long b) {
    asm("fma.rn.f32x2 %0,%1,%2,%0;" : "+l"(c) : "l"(a), "l"(b));
}
__device__ __forceinline__ float2 unpk(unsigned long long v) {
    float2 r;
    asm("mov.b64 {%0,%1},%2;" : "=f"(r.x), "=f"(r.y) : "l"(v));
    return r;
}

// ---------------- K0: scale[b][c] = dot(cond[b], w_norm[c]) + 1 ----------------
__global__ void k_scale(const float* __restrict__ cond, const float* __restrict__ w_norm) {
    int b = blockIdx.x, c = threadIdx.x;
    const float4* cv = (const float4*)(cond + b * DM);
    const float4* wv = (const float4*)(w_norm + c * DM);
    float s = 0.f;
#pragma unroll 16
    for (int k = 0; k < DM / 4; k++) {
        float4 a = cv[k], w = wv[k];
        s += a.x * w.x + a.y * w.y + a.z * w.z + a.w * w.w;
    }
    g_scale[b * DM + c] = s + 1.f;
}

// ---------------- K1: RMS norm per token ----------------
__global__ void k_rms(const float* __restrict__ x) {
    int t = blockIdx.x;
    int c = threadIdx.x;
    int b = t / (HH * WW);
    float v = x[t * DM + c];
    float sq = v * v;
#pragma unroll
    for (int o = 16; o > 0; o >>= 1) sq += __shfl_xor_sync(0xffffffffu, sq, o);
    __shared__ float ws[8];
    if ((c & 31) == 0) ws[c >> 5] = sq;
    __syncthreads();
    float tot = ws[0] + ws[1] + ws[2] + ws[3] + ws[4] + ws[5] + ws[6] + ws[7];
    float inv = rsqrtf(tot * (1.f / DM) + EPS);
    g_xn[t * DM + c] = v * g_scale[b * DM + c] * inv;
}

// ---------------- qkv GEMM (128x128 tile, FFMA2) + fused rotary/permute epilogue --------
// C[M=4608, N=768] = A[4608,256] @ B[768,256]^T, then per-element route to g_q/g_k/g_v
// in [b][h][i][j][e] layout with rotary applied to q,k (and q * 0.125).
__global__ void __launch_bounds__(256) k_gemm_qkv_rope(const float* __restrict__ A,
                                                       const float* __restrict__ B,
                                                       const float* __restrict__ pos) {
    constexpr int BM = 128, BK = 16, BN = 128;
    constexpr int K = DM, N = 3 * DM;
    __shared__ float As[2][BK][BM];
    __shared__ float Bs[2][BK][BN];
    extern __shared__ float Cs[];            // [128][132]

    int tid = threadIdx.x;
    int m0 = blockIdx.y * BM, n0 = blockIdx.x * BN;

    int arow = tid >> 1, akh = (tid & 1) * 8;
    const float* Ag = A + (size_t)(m0 + arow) * K + akh;
    const float* Bg = B + (size_t)(n0 + arow) * K + akh;

    float ra[8], rb[8];
    {
        float4 v0 = *(const float4*)(Ag + 0);
        float4 v1 = *(const float4*)(Ag + 4);
        ra[0]=v0.x; ra[1]=v0.y; ra[2]=v0.z; ra[3]=v0.w;
        ra[4]=v1.x; ra[5]=v1.y; ra[6]=v1.z; ra[7]=v1.w;
        float4 w0 = *(const float4*)(Bg + 0);
        float4 w1 = *(const float4*)(Bg + 4);
        rb[0]=w0.x; rb[1]=w0.y; rb[2]=w0.z; rb[3]=w0.w;
        rb[4]=w1.x; rb[5]=w1.y; rb[6]=w1.z; rb[7]=w1.w;
    }
#pragma unroll
    for (int c = 0; c < 8; c++) { As[0][akh + c][arow] = ra[c]; Bs[0][akh + c][arow] = rb[c]; }
    __syncthreads();

    int tx = tid & 15, ty = tid >> 4;
    unsigned long long acc[8][4];
#pragma unroll
    for (int i = 0; i < 8; i++)
#pragma unroll
        for (int j = 0; j < 4; j++) acc[i][j] = 0ull;

    int nkt = K / BK;
    int buf = 0;
    for (int t = 0; t < nkt; t++) {
        if (t + 1 < nkt) {
            int k0 = (t + 1) * BK;
            float4 v0 = *(const float4*)(Ag + k0);
            float4 v1 = *(const float4*)(Ag + k0 + 4);
            ra[0]=v0.x; ra[1]=v0.y; ra[2]=v0.z; ra[3]=v0.w;
            ra[4]=v1.x; ra[5]=v1.y; ra[6]=v1.z; ra[7]=v1.w;
            float4 w0 = *(const float4*)(Bg + k0);
            float4 w1 = *(const float4*)(Bg + k0 + 4);
            rb[0]=w0.x; rb[1]=w0.y; rb[2]=w0.z; rb[3]=w0.w;
            rb[4]=w1.x; rb[5]=w1.y; rb[6]=w1.z; rb[7]=w1.w;
        }
#pragma unroll
        for (int kk = 0; kk < BK; kk++) {
            float4 a0 = *(const float4*)&As[buf][kk][ty * 8];
            float4 a1 = *(const float4*)&As[buf][kk][ty * 8 + 4];
            ulonglong2 b0 = *(const ulonglong2*)&Bs[buf][kk][tx * 4];
            ulonglong2 b1 = *(const ulonglong2*)&Bs[buf][kk][64 + tx * 4];
            unsigned long long ad[8];
            ad[0]=dupf(a0.x); ad[1]=dupf(a0.y); ad[2]=dupf(a0.z); ad[3]=dupf(a0.w);
            ad[4]=dupf(a1.x); ad[5]=dupf(a1.y); ad[6]=dupf(a1.z); ad[7]=dupf(a1.w);
#pragma unroll
            for (int i = 0; i < 8; i++) {
                ffma2(acc[i][0], ad[i], b0.x);
                ffma2(acc[i][1], ad[i], b0.y);
                ffma2(acc[i][2], ad[i], b1.x);
                ffma2(acc[i][3], ad[i], b1.y);
            }
        }
        if (t + 1 < nkt) {
            int nb = buf ^ 1;
#pragma unroll
            for (int c = 0; c < 8; c++) { As[nb][akh + c][arow] = ra[c]; Bs[nb][akh + c][arow] = rb[c]; }
            __syncthreads();
            buf = nb;
        }
    }

    // stage C tile in smem
#pragma unroll
    for (int i = 0; i < 8; i++) {
        int r = ty * 8 + i;
        float2 p0 = unpk(acc[i][0]), p1 = unpk(acc[i][1]);
        float2 p2 = unpk(acc[i][2]), p3 = unpk(acc[i][3]);
        *(float4*)&Cs[r * 132 + tx * 4]      = make_float4(p0.x, p0.y, p1.x, p1.y);
        *(float4*)&Cs[r * 132 + 64 + tx * 4] = make_float4(p2.x, p2.y, p3.x, p3.y);
    }
    __syncthreads();

    // rope + permute readout: thread -> (row, half), 64 channels of one head
    {
        int r = tid >> 1, half = tid & 1;
        int token = m0 + r;
        int b = token / (HH * WW);
        int ij = token - b * (HH * WW);
        int i = ij / WW, j = ij - i * WW;
        int c_lo = n0 + half * 64;
        int part = c_lo >> 8;            // 0=q 1=k 2=v
        int rem  = c_lo & 255;
        int h = rem >> 6;
        float* dst = (part == 0 ? g_q : part == 1 ? g_k : g_v)
                   + ((size_t)((b * NHEAD + h) * HH + i) * WW + j) * EH;
        const float* src = Cs + r * 132 + half * 64;

        if (part == 2) {
#pragma unroll
            for (int e4 = 0; e4 < 16; e4++)
                *(float4*)(dst + e4 * 4) = *(const float4*)(src + e4 * 4);
        } else {
            float gh = pos[(i * WW + j) * 2 + 0];
            float gw = pos[(i * WW + j) * 2 + 1];
            float fr[8];
#pragma unroll
            for (int fi = 0; fi < 8; fi++)
                fr[fi] = 3.14159265358979323846f * exp10f((float)fi * 0.125f);
            float ov[32];
#pragma unroll
            for (int e = 0; e < 16; e++) {
                float f  = fr[e & 7];
                float p  = (e < 8) ? gh : gw;
                float an = p * f;
                float cs = cosf(an), sn = sinf(an);
                float x1 = src[e], x2 = src[e + 16];
                ov[e]      = x1 * cs - x2 * sn;
                ov[e + 16] = x2 * cs + x1 * sn;
            }
            float sc = (part == 0) ? 0.125f : 1.f;
#pragma unroll
            for (int e4 = 0; e4 < 8; e4++)
                *(float4*)(dst + e4 * 4) = make_float4(ov[e4*4]*sc, ov[e4*4+1]*sc,
                                                       ov[e4*4+2]*sc, ov[e4*4+3]*sc);
#pragma unroll
            for (int e4 = 8; e4 < 16; e4++) {
                float4 v = *(const float4*)(src + e4 * 4);
                *(float4*)(dst + e4 * 4) = make_float4(v.x*sc, v.y*sc, v.z*sc, v.w*sc);
            }
        }
    }
}

// ---------------- plain FFMA2 GEMM for output projection (BN=64) ----------------
__global__ void __launch_bounds__(256) k_gemm_out(const float* __restrict__ A,
                                                  const float* __restrict__ B,
                                                  const float* __restrict__ Sk,
                                                  float* __restrict__ C) {
    constexpr int BK = 16, K = DM, N = DM;
    __shared__ float As[2][BK][128];
    __shared__ float Bs[2][BK][64];

    int tid = threadIdx.x;
    int m0 = blockIdx.y * 128, n0 = blockIdx.x * 64;

    int arow = tid >> 1, akh = (tid & 1) * 8;
    int brow = tid >> 2, bkh = (tid & 3) * 4;
    const float* Ag = A + (size_t)(m0 + arow) * K + akh;
    const float* Bg = B + (size_t)(n0 + brow) * K + bkh;

    float ra[8], rb[4];
    {
        float4 v0 = *(const float4*)(Ag + 0);
        float4 v1 = *(const float4*)(Ag + 4);
        ra[0]=v0.x; ra[1]=v0.y; ra[2]=v0.z; ra[3]=v0.w;
        ra[4]=v1.x; ra[5]=v1.y; ra[6]=v1.z; ra[7]=v1.w;
        float4 w0 = *(const float4*)(Bg + 0);
        rb[0]=w0.x; rb[1]=w0.y; rb[2]=w0.z; rb[3]=w0.w;
    }
#pragma unroll
    for (int c = 0; c < 8; c++) As[0][akh + c][arow] = ra[c];
#pragma unroll
    for (int c = 0; c < 4; c++) Bs[0][bkh + c][brow] = rb[c];
    __syncthreads();

    int tx = tid & 15, ty = tid >> 4;
    unsigned long long acc[8][2];
#pragma unroll
    for (int i = 0; i < 8; i++) { acc[i][0] = 0ull; acc[i][1] = 0ull; }

    int nkt = K / BK;
    int buf = 0;
    for (int t = 0; t < nkt; t++) {
        if (t + 1 < nkt) {
            int k0 = (t + 1) * BK;
            float4 v0 = *(const float4*)(Ag + k0);
            float4 v1 = *(const float4*)(Ag + k0 + 4);
            ra[0]=v0.x; ra[1]=v0.y; ra[2]=v0.z; ra[3]=v0.w;
            ra[4]=v1.x; ra[5]=v1.y; ra[6]=v1.z; ra[7]=v1.w;
            float4 w0 = *(const float4*)(Bg + k0);
            rb[0]=w0.x; rb[1]=w0.y; rb[2]=w0.z; rb[3]=w0.w;
        }
#pragma unroll
        for (int kk = 0; kk < BK; kk++) {
            float4 a0 = *(const float4*)&As[buf][kk][ty * 8];
            float4 a1 = *(const float4*)&As[buf][kk][ty * 8 + 4];
            ulonglong2 b0 = *(const ulonglong2*)&Bs[buf][kk][tx * 4];
            unsigned long long ad[8];
            ad[0]=dupf(a0.x); ad[1]=dupf(a0.y); ad[2]=dupf(a0.z); ad[3]=dupf(a0.w);
            ad[4]=dupf(a1.x); ad[5]=dupf(a1.y); ad[6]=dupf(a1.z); ad[7]=dupf(a1.w);
#pragma unroll
            for (int i = 0; i < 8; i++) {
                ffma2(acc[i][0], ad[i], b0.x);
                ffma2(acc[i][1], ad[i], b0.y);
            }
        }
        if (t + 1 < nkt) {
            int nb = buf ^ 1;
#pragma unroll
            for (int c = 0; c < 8; c++) As[nb][akh + c][arow] = ra[c];
#pragma unroll
            for (int c = 0; c < 4; c++) Bs[nb][bkh + c][brow] = rb[c];
            __syncthreads();
            buf = nb;
        }
    }

#pragma unroll
    for (int i = 0; i < 8; i++) {
        int m = m0 + ty * 8 + i, nn = n0 + tx * 4;
        float2 p0 = unpk(acc[i][0]), p1 = unpk(acc[i][1]);
        float4 s = *(const float4*)&Sk[(size_t)m * N + nn];
        *(float4*)&C[(size_t)m * N + nn] =
            make_float4(p0.x + s.x, p0.y + s.y, p1.x + s.z, p1.y + s.w);
    }
}

// ---------------- attention: 2x8 query tile, smem-staged halo, lane=position ----------
// dyn smem: ks[112][68] | vs[112][68] | qs[16][64] | as[16][64]
#define KS_STRIDE 68
#define HALO 112           // 8 rows x 14 cols
__global__ void __launch_bounds__(128) k_attn() {
    extern __shared__ float sm[];
    float* ks  = sm;
    float* vs  = sm + HALO * KS_STRIDE;
    float* qs  = sm + 2 * HALO * KS_STRIDE;
    float* as_ = qs + 16 * 64;

    int j0 = blockIdx.x * 8;
    int i0 = blockIdx.y * 2;
    int bh = blockIdx.z;
    int b = bh >> 2, h = bh & 3;
    int tid = threadIdx.x;
    int warp = tid >> 5, lane = tid & 31;

    int r0 = min(max(i0 - 3, 0), HH - 8);
    int c0 = min(max(j0 - 3, 0), WW - 14);

    const float* kg = g_k + (size_t)(b * NHEAD + h) * HH * WW * EH;
    const float* vg = g_v + (size_t)(b * NHEAD + h) * HH * WW * EH;
    const float* qg = g_q + (size_t)(b * NHEAD + h) * HH * WW * EH;

    // fill K,V halo (coalesced float4)
    for (int idx = tid; idx < HALO * 16; idx += 128) {
        int p = idx >> 4, c4 = idx & 15;
        int r = r0 + p / 14, c = c0 + p % 14;
        size_t goff = ((size_t)r * WW + c) * EH + c4 * 4;
        *(float4*)(ks + p * KS_STRIDE + c4 * 4) = *(const float4*)(kg + goff);
        *(float4*)(vs + p * KS_STRIDE + c4 * 4) = *(const float4*)(vg + goff);
    }
    // fill q
    for (int idx = tid; idx < 16 * 16; idx += 128) {
        int qi = idx >> 4, c4 = idx & 15;
        int iq = i0 + (qi >> 3), jq = j0 + (qi & 7);
        *(float4*)(qs + qi * 64 + c4 * 4) =
            *(const float4*)(qg + ((size_t)iq * WW + jq) * EH + c4 * 4);
    }
    __syncthreads();

#pragma unroll
    for (int s = 0; s < 4; s++) {
        int qi = warp * 4 + s;
        int di = qi >> 3, dj = qi & 7;
        int iq = i0 + di, jq = j0 + dj;
        int sh = min(max(iq - 3, 0), HH - 7);
        int sw = min(max(jq - 3, 0), WW - 7);
        int offq = (sh - r0) * 14 + (sw - c0);

        // QK: lane owns positions pA=lane, pB=lane+32
        int pA = lane, pB = lane + 32;
        int hpA = offq + (pA / 7) * 14 + pA % 7;
        int hpB = offq + (pB / 7) * 14 + pB % 7;
        const float* kA = ks + hpA * KS_STRIDE;
        const float* kB = ks + hpB * KS_STRIDE;
        const float* qrow = qs + qi * 64;
        unsigned long long accA = 0ull, accB = 0ull;
#pragma unroll
        for (int e = 0; e < 64; e += 2) {
            unsigned long long qp = *(const unsigned long long*)(qrow + e);
            unsigned long long ka = *(const unsigned long long*)(kA + e);
            unsigned long long kb = *(const unsigned long long*)(kB + e);
            ffma2(accA, qp, ka);
            ffma2(accB, qp, kb);
        }
        float2 ua = unpk(accA), ub = unpk(accB);
        float sA = ua.x + ua.y;
        float sB = (lane < 17) ? (ub.x + ub.y) : -1e30f;

        // softmax across 49 lane-held scores
        float mx = fmaxf(sA, sB);
#pragma unroll
        for (int o = 16; o > 0; o >>= 1) mx = fmaxf(mx, __shfl_xor_sync(0xffffffffu, mx, o));
        float eA = __expf(sA - mx);
        float eB = (lane < 17) ? __expf(sB - mx) : 0.f;
        float sum = eA + eB;
#pragma unroll
        for (int o = 16; o > 0; o >>= 1) sum += __shfl_xor_sync(0xffffffffu, sum, o);
        float inv = 1.f / sum;

        as_[qi * 64 + lane] = eA * inv;
        if (lane < 17) as_[qi * 64 + 32 + lane] = eB * inv;
        __syncwarp();

        // AV: lane owns dim pair (2*lane, 2*lane+1)
        unsigned long long acc = 0ull;
#pragma unroll
        for (int p = 0; p < 49; p++) {
            int hp = offq + (p / 7) * 14 + (p % 7);
            float a = as_[qi * 64 + p];
            unsigned long long av = *(const unsigned long long*)(vs + hp * KS_STRIDE + 2 * lane);
            ffma2(acc, dupf(a), av);
        }
        float2 r = unpk(acc);
        int tok = b * (HH * WW) + iq * WW + jq;
        *(float2*)(g_o + (size_t)tok * DM + h * EH + 2 * lane) = r;
        __syncwarp();
    }
}

// ---------------- launch ----------------
extern "C" void kernel_launch(void* const* d_in, const int* in_sizes, int n_in,
                              void* d_out, int out_size) {
    const float* x      = (const float*)d_in[0];
    const float* pos    = (const float*)d_in[1];
    const float* cond   = (const float*)d_in[2];
    const float* w_norm = (const float*)d_in[3];
    const float* w_qkv  = (const float*)d_in[4];
    const float* w_out  = (const float*)d_in[5];
    float* out = (float*)d_out;

    k_scale<<<NB, 256>>>(cond, w_norm);
    k_rms<<<TOK, 256>>>(x);

    {
        float* gxn; cudaGetSymbolAddress((void**)&gxn, g_xn);
        size_t cs_bytes = 128 * 132 * sizeof(float);   // 67584
        cudaFuncSetAttribute(k_gemm_qkv_rope,
                             cudaFuncAttributeMaxDynamicSharedMemorySize, (int)cs_bytes);
        dim3 g1((3 * DM) / 128, TOK / 128);
        k_gemm_qkv_rope<<<g1, 256, cs_bytes>>>(gxn, w_qkv, pos);
    }

    {
        size_t sm_bytes = (2 * HALO * KS_STRIDE + 16 * 64 + 16 * 64) * sizeof(float); // 69120
        cudaFuncSetAttribute(k_attn,
                             cudaFuncAttributeMaxDynamicSharedMemorySize, (int)sm_bytes);
        dim3 g2(WW / 8, HH / 2, NB * NHEAD);
        k_attn<<<g2, 128, sm_bytes>>>();
    }

    {
        float* go; cudaGetSymbolAddress((void**)&go, g_o);
        dim3 g3(DM / 64, TOK / 128);
        k_gemm_out<<<g3, 256>>>(go, w_out, x, out);
    }
}

// round 6
// speedup vs baseline: 1.0604x; 1.0604x over previous
#include <cuda_runtime.h>

#define TOK   4608      // n*H*W
#define NB    2
#define HH    48
#define WW    48
#define DM    256
#define NHEAD 4
#define EH    64
#define EPS   1e-6f

// ---------------- scratch ----------------
__device__ float g_scale[NB * DM];
__device__ float g_rfac [TOK];
__device__ float g_q   [NB * NHEAD * HH * WW * EH];
__device__ float g_k   [NB * NHEAD * HH * WW * EH];
__device__ float g_v   [NB * NHEAD * HH * WW * EH];
__device__ float g_o   [TOK * DM];

// ---------------- packed f32x2 helpers ----------------
__device__ __forceinline__ unsigned long long dupf(float x) {
    unsigned long long r;
    asm("mov.b64 %0,{%1,%2};" : "=l"(r) : "f"(x), "f"(x));
    return r;
}
__device__ __forceinline__ void ffma2(unsigned long long& c, unsigned long long a, unsigned long long b) {
    asm("fma.rn.f32x2 %0,%1,%2,%0;" : "+l"(c) : "l"(a), "l"(b));
}
__device__ __forceinline__ float2 unpk(unsigned long long v) {
    float2 r;
    asm("mov.b64 {%0,%1},%2;" : "=f"(r.x), "=f"(r.y) : "l"(v));
    return r;
}

// ---------------- K0: scale[b][c] = dot(cond[b], w_norm[c]) + 1 ----------------
__global__ void k_scale(const float* __restrict__ cond, const float* __restrict__ w_norm) {
    int b = blockIdx.x, c = threadIdx.x;
    const float4* cv = (const float4*)(cond + b * DM);
    const float4* wv = (const float4*)(w_norm + c * DM);
    float s = 0.f;
#pragma unroll 16
    for (int k = 0; k < DM / 4; k++) {
        float4 a = cv[k], w = wv[k];
        s += a.x * w.x + a.y * w.y + a.z * w.z + a.w * w.w;
    }
    g_scale[b * DM + c] = s + 1.f;
}

// ---------------- K1: per-token rsqrt(mean(x^2)+eps), one warp per token ----------------
__global__ void __launch_bounds__(256) k_rmsfac(const float* __restrict__ x) {
    int warp = threadIdx.x >> 5, lane = threadIdx.x & 31;
    int t = blockIdx.x * 8 + warp;
    const float4* xv = (const float4*)(x + (size_t)t * DM);
    float4 a = xv[lane], b = xv[lane + 32];
    float sq = a.x*a.x + a.y*a.y + a.z*a.z + a.w*a.w
             + b.x*b.x + b.y*b.y + b.z*b.z + b.w*b.w;
#pragma unroll
    for (int o = 16; o > 0; o >>= 1) sq += __shfl_xor_sync(0xffffffffu, sq, o);
    if (lane == 0) g_rfac[t] = rsqrtf(sq * (1.f / DM) + EPS);
}

// ---------------- qkv GEMM (fused rms-norm A-load, FFMA2) + rotary/permute epilogue ----
__global__ void __launch_bounds__(256) k_gemm_qkv_rope(const float* __restrict__ X,
                                                       const float* __restrict__ B,
                                                       const float* __restrict__ pos) {
    constexpr int BM = 128, BK = 16, BN = 128;
    constexpr int K = DM;
    __shared__ float As[2][BK][BM];
    __shared__ float Bs[2][BK][BN];
    extern __shared__ float Cs[];            // [128][132]

    int tid = threadIdx.x;
    int m0 = blockIdx.y * BM, n0 = blockIdx.x * BN;

    int arow = tid >> 1, akh = (tid & 1) * 8;
    int tokA = m0 + arow;
    int bA = tokA / (HH * WW);
    const float* Ag = X + (size_t)tokA * K + akh;
    const float* Sg = g_scale + bA * DM + akh;
    float rfac = g_rfac[tokA];
    const float* Bg = B + (size_t)(n0 + arow) * K + akh;

    float ra[8], rb[8];
    {
        float4 v0 = *(const float4*)(Ag + 0);
        float4 v1 = *(const float4*)(Ag + 4);
        float4 s0 = *(const float4*)(Sg + 0);
        float4 s1 = *(const float4*)(Sg + 4);
        ra[0]=v0.x*s0.x*rfac; ra[1]=v0.y*s0.y*rfac; ra[2]=v0.z*s0.z*rfac; ra[3]=v0.w*s0.w*rfac;
        ra[4]=v1.x*s1.x*rfac; ra[5]=v1.y*s1.y*rfac; ra[6]=v1.z*s1.z*rfac; ra[7]=v1.w*s1.w*rfac;
        float4 w0 = *(const float4*)(Bg + 0);
        float4 w1 = *(const float4*)(Bg + 4);
        rb[0]=w0.x; rb[1]=w0.y; rb[2]=w0.z; rb[3]=w0.w;
        rb[4]=w1.x; rb[5]=w1.y; rb[6]=w1.z; rb[7]=w1.w;
    }
#pragma unroll
    for (int c = 0; c < 8; c++) { As[0][akh + c][arow] = ra[c]; Bs[0][akh + c][arow] = rb[c]; }
    __syncthreads();

    int tx = tid & 15, ty = tid >> 4;
    unsigned long long acc[8][4];
#pragma unroll
    for (int i = 0; i < 8; i++)
#pragma unroll
        for (int j = 0; j < 4; j++) acc[i][j] = 0ull;

    int nkt = K / BK;
    int buf = 0;
    for (int t = 0; t < nkt; t++) {
        if (t + 1 < nkt) {
            int k0 = (t + 1) * BK;
            float4 v0 = *(const float4*)(Ag + k0);
            float4 v1 = *(const float4*)(Ag + k0 + 4);
            float4 s0 = *(const float4*)(Sg + k0);
            float4 s1 = *(const float4*)(Sg + k0 + 4);
            ra[0]=v0.x*s0.x*rfac; ra[1]=v0.y*s0.y*rfac; ra[2]=v0.z*s0.z*rfac; ra[3]=v0.w*s0.w*rfac;
            ra[4]=v1.x*s1.x*rfac; ra[5]=v1.y*s1.y*rfac; ra[6]=v1.z*s1.z*rfac; ra[7]=v1.w*s1.w*rfac;
            float4 w0 = *(const float4*)(Bg + k0);
            float4 w1 = *(const float4*)(Bg + k0 + 4);
            rb[0]=w0.x; rb[1]=w0.y; rb[2]=w0.z; rb[3]=w0.w;
            rb[4]=w1.x; rb[5]=w1.y; rb[6]=w1.z; rb[7]=w1.w;
        }
#pragma unroll
        for (int kk = 0; kk < BK; kk++) {
            float4 a0 = *(const float4*)&As[buf][kk][ty * 8];
            float4 a1 = *(const float4*)&As[buf][kk][ty * 8 + 4];
            ulonglong2 b0 = *(const ulonglong2*)&Bs[buf][kk][tx * 4];
            ulonglong2 b1 = *(const ulonglong2*)&Bs[buf][kk][64 + tx * 4];
            unsigned long long ad[8];
            ad[0]=dupf(a0.x); ad[1]=dupf(a0.y); ad[2]=dupf(a0.z); ad[3]=dupf(a0.w);
            ad[4]=dupf(a1.x); ad[5]=dupf(a1.y); ad[6]=dupf(a1.z); ad[7]=dupf(a1.w);
#pragma unroll
            for (int i = 0; i < 8; i++) {
                ffma2(acc[i][0], ad[i], b0.x);
                ffma2(acc[i][1], ad[i], b0.y);
                ffma2(acc[i][2], ad[i], b1.x);
                ffma2(acc[i][3], ad[i], b1.y);
            }
        }
        if (t + 1 < nkt) {
            int nb = buf ^ 1;
#pragma unroll
            for (int c = 0; c < 8; c++) { As[nb][akh + c][arow] = ra[c]; Bs[nb][akh + c][arow] = rb[c]; }
            __syncthreads();
            buf = nb;
        }
    }

#pragma unroll
    for (int i = 0; i < 8; i++) {
        int r = ty * 8 + i;
        float2 p0 = unpk(acc[i][0]), p1 = unpk(acc[i][1]);
        float2 p2 = unpk(acc[i][2]), p3 = unpk(acc[i][3]);
        *(float4*)&Cs[r * 132 + tx * 4]      = make_float4(p0.x, p0.y, p1.x, p1.y);
        *(float4*)&Cs[r * 132 + 64 + tx * 4] = make_float4(p2.x, p2.y, p3.x, p3.y);
    }
    __syncthreads();

    {
        int r = tid >> 1, half = tid & 1;
        int token = m0 + r;
        int b = token / (HH * WW);
        int ij = token - b * (HH * WW);
        int i = ij / WW, j = ij - i * WW;
        int c_lo = n0 + half * 64;
        int part = c_lo >> 8;            // 0=q 1=k 2=v
        int rem  = c_lo & 255;
        int h = rem >> 6;
        float* dst = (part == 0 ? g_q : part == 1 ? g_k : g_v)
                   + ((size_t)((b * NHEAD + h) * HH + i) * WW + j) * EH;
        const float* src = Cs + r * 132 + half * 64;

        if (part == 2) {
#pragma unroll
            for (int e4 = 0; e4 < 16; e4++)
                *(float4*)(dst + e4 * 4) = *(const float4*)(src + e4 * 4);
        } else {
            float gh = pos[(i * WW + j) * 2 + 0];
            float gw = pos[(i * WW + j) * 2 + 1];
            float fr[8];
#pragma unroll
            for (int fi = 0; fi < 8; fi++)
                fr[fi] = 3.14159265358979323846f * exp10f((float)fi * 0.125f);
            float ov[32];
#pragma unroll
            for (int e = 0; e < 16; e++) {
                float f  = fr[e & 7];
                float p  = (e < 8) ? gh : gw;
                float an = p * f;
                float cs = cosf(an), sn = sinf(an);
                float x1 = src[e], x2 = src[e + 16];
                ov[e]      = x1 * cs - x2 * sn;
                ov[e + 16] = x2 * cs + x1 * sn;
            }
            float sc = (part == 0) ? 0.125f : 1.f;
#pragma unroll
            for (int e4 = 0; e4 < 8; e4++)
                *(float4*)(dst + e4 * 4) = make_float4(ov[e4*4]*sc, ov[e4*4+1]*sc,
                                                       ov[e4*4+2]*sc, ov[e4*4+3]*sc);
#pragma unroll
            for (int e4 = 8; e4 < 16; e4++) {
                float4 v = *(const float4*)(src + e4 * 4);
                *(float4*)(dst + e4 * 4) = make_float4(v.x*sc, v.y*sc, v.z*sc, v.w*sc);
            }
        }
    }
}

// ---------------- plain FFMA2 GEMM for output projection (BN=64) ----------------
__global__ void __launch_bounds__(256) k_gemm_out(const float* __restrict__ A,
                                                  const float* __restrict__ B,
                                                  const float* __restrict__ Sk,
                                                  float* __restrict__ C) {
    constexpr int BK = 16, K = DM, N = DM;
    __shared__ float As[2][BK][128];
    __shared__ float Bs[2][BK][64];

    int tid = threadIdx.x;
    int m0 = blockIdx.y * 128, n0 = blockIdx.x * 64;

    int arow = tid >> 1, akh = (tid & 1) * 8;
    int brow = tid >> 2, bkh = (tid & 3) * 4;
    const float* Ag = A + (size_t)(m0 + arow) * K + akh;
    const float* Bg = B + (size_t)(n0 + brow) * K + bkh;

    float ra[8], rb[4];
    {
        float4 v0 = *(const float4*)(Ag + 0);
        float4 v1 = *(const float4*)(Ag + 4);
        ra[0]=v0.x; ra[1]=v0.y; ra[2]=v0.z; ra[3]=v0.w;
        ra[4]=v1.x; ra[5]=v1.y; ra[6]=v1.z; ra[7]=v1.w;
        float4 w0 = *(const float4*)(Bg + 0);
        rb[0]=w0.x; rb[1]=w0.y; rb[2]=w0.z; rb[3]=w0.w;
    }
#pragma unroll
    for (int c = 0; c < 8; c++) As[0][akh + c][arow] = ra[c];
#pragma unroll
    for (int c = 0; c < 4; c++) Bs[0][bkh + c][brow] = rb[c];
    __syncthreads();

    int tx = tid & 15, ty = tid >> 4;
    unsigned long long acc[8][2];
#pragma unroll
    for (int i = 0; i < 8; i++) { acc[i][0] = 0ull; acc[i][1] = 0ull; }

    int nkt = K / BK;
    int buf = 0;
    for (int t = 0; t < nkt; t++) {
        if (t + 1 < nkt) {
            int k0 = (t + 1) * BK;
            float4 v0 = *(const float4*)(Ag + k0);
            float4 v1 = *(const float4*)(Ag + k0 + 4);
            ra[0]=v0.x; ra[1]=v0.y; ra[2]=v0.z; ra[3]=v0.w;
            ra[4]=v1.x; ra[5]=v1.y; ra[6]=v1.z; ra[7]=v1.w;
            float4 w0 = *(const float4*)(Bg + k0);
            rb[0]=w0.x; rb[1]=w0.y; rb[2]=w0.z; rb[3]=w0.w;
        }
#pragma unroll
        for (int kk = 0; kk < BK; kk++) {
            float4 a0 = *(const float4*)&As[buf][kk][ty * 8];
            float4 a1 = *(const float4*)&As[buf][kk][ty * 8 + 4];
            ulonglong2 b0 = *(const ulonglong2*)&Bs[buf][kk][tx * 4];
            unsigned long long ad[8];
            ad[0]=dupf(a0.x); ad[1]=dupf(a0.y); ad[2]=dupf(a0.z); ad[3]=dupf(a0.w);
            ad[4]=dupf(a1.x); ad[5]=dupf(a1.y); ad[6]=dupf(a1.z); ad[7]=dupf(a1.w);
#pragma unroll
            for (int i = 0; i < 8; i++) {
                ffma2(acc[i][0], ad[i], b0.x);
                ffma2(acc[i][1], ad[i], b0.y);
            }
        }
        if (t + 1 < nkt) {
            int nb = buf ^ 1;
#pragma unroll
            for (int c = 0; c < 8; c++) As[nb][akh + c][arow] = ra[c];
#pragma unroll
            for (int c = 0; c < 4; c++) Bs[nb][bkh + c][brow] = rb[c];
            __syncthreads();
            buf = nb;
        }
    }

#pragma unroll
    for (int i = 0; i < 8; i++) {
        int m = m0 + ty * 8 + i, nn = n0 + tx * 4;
        float2 p0 = unpk(acc[i][0]), p1 = unpk(acc[i][1]);
        float4 s = *(const float4*)&Sk[(size_t)m * N + nn];
        *(float4*)&C[(size_t)m * N + nn] =
            make_float4(p0.x + s.x, p0.y + s.y, p1.x + s.z, p1.y + s.w);
    }
}

// ---------------- attention: 2x8 query tile, K-halo in smem (stride 66), V via L1 ------
#define KSS  66
#define HALO 112           // 8 rows x 14 cols
__global__ void __launch_bounds__(256) k_attn() {
    extern __shared__ float sm[];
    float* ks  = sm;                       // [112][66]
    float* qs  = sm + HALO * KSS;          // [16][64]
    float* as_ = qs + 16 * 64;             // [16][64]

    int j0 = blockIdx.x * 8;
    int i0 = blockIdx.y * 2;
    int bh = blockIdx.z;
    int b = bh >> 2, h = bh & 3;
    int tid = threadIdx.x;
    int warp = tid >> 5, lane = tid & 31;

    int r0 = min(max(i0 - 3, 0), HH - 8);
    int c0 = min(max(j0 - 3, 0), WW - 14);

    const float* kg = g_k + (size_t)(b * NHEAD + h) * HH * WW * EH;
    const float* vg = g_v + (size_t)(b * NHEAD + h) * HH * WW * EH;
    const float* qg = g_q + (size_t)(b * NHEAD + h) * HH * WW * EH;

    // K halo: coalesced float4 gmem loads, scalar smem stores (stride 66)
    for (int idx = tid; idx < HALO * 16; idx += 256) {
        int p = idx >> 4, c4 = idx & 15;
        int r = r0 + p / 14, c = c0 + p % 14;
        float4 v = *(const float4*)(kg + ((size_t)r * WW + c) * EH + c4 * 4);
        float* d = ks + p * KSS + c4 * 4;
        d[0] = v.x; d[1] = v.y; d[2] = v.z; d[3] = v.w;
    }
    for (int idx = tid; idx < 16 * 16; idx += 256) {
        int qi = idx >> 4, c4 = idx & 15;
        int iq = i0 + (qi >> 3), jq = j0 + (qi & 7);
        *(float4*)(qs + qi * 64 + c4 * 4) =
            *(const float4*)(qg + ((size_t)iq * WW + jq) * EH + c4 * 4);
    }
    __syncthreads();

#pragma unroll
    for (int s = 0; s < 2; s++) {
        int qi = warp * 2 + s;
        int di = qi >> 3, dj = qi & 7;
        int iq = i0 + di, jq = j0 + dj;
        int sh = min(max(iq - 3, 0), HH - 7);
        int sw = min(max(jq - 3, 0), WW - 7);
        int offq = (sh - r0) * 14 + (sw - c0);

        // QK: lane owns positions pA=lane, pB=lane+32 (pB clamped: only lanes<17 valid)
        int pA = lane;
        int pB = min(lane + 32, 48);            // clamp keeps smem address in-bounds
        int hpA = offq + (pA / 7) * 14 + pA % 7;
        int hpB = offq + (pB / 7) * 14 + pB % 7;
        const float* kA = ks + hpA * KSS;
        const float* kB = ks + hpB * KSS;
        const float* qrow = qs + qi * 64;
        unsigned long long accA = 0ull, accB = 0ull;
#pragma unroll
        for (int e = 0; e < 64; e += 2) {
            unsigned long long qp = *(const unsigned long long*)(qrow + e);
            unsigned long long ka = *(const unsigned long long*)(kA + e);
            unsigned long long kb = *(const unsigned long long*)(kB + e);
            ffma2(accA, qp, ka);
            ffma2(accB, qp, kb);
        }
        float2 ua = unpk(accA), ub = unpk(accB);
        float sA = ua.x + ua.y;
        float sB = (lane < 17) ? (ub.x + ub.y) : -1e30f;

        float mx = fmaxf(sA, sB);
#pragma unroll
        for (int o = 16; o > 0; o >>= 1) mx = fmaxf(mx, __shfl_xor_sync(0xffffffffu, mx, o));
        float eA = __expf(sA - mx);
        float eB = (lane < 17) ? __expf(sB - mx) : 0.f;
        float sum = eA + eB;
#pragma unroll
        for (int o = 16; o > 0; o >>= 1) sum += __shfl_xor_sync(0xffffffffu, sum, o);
        float inv = 1.f / sum;

        as_[qi * 64 + lane] = eA * inv;
        if (lane < 17) as_[qi * 64 + 32 + lane] = eB * inv;
        __syncwarp();

        // AV: V straight from gmem (L1-resident; one coalesced row per p)
        unsigned long long acc = 0ull;
#pragma unroll
        for (int p = 0; p < 49; p++) {
            int gr = (sh + p / 7) * WW + (sw + p % 7);
            float a = as_[qi * 64 + p];
            unsigned long long av = *(const unsigned long long*)(vg + (size_t)gr * EH + 2 * lane);
            ffma2(acc, dupf(a), av);
        }
        float2 r = unpk(acc);
        int tok = b * (HH * WW) + iq * WW + jq;
        *(float2*)(g_o + (size_t)tok * DM + h * EH + 2 * lane) = r;
        __syncwarp();
    }
}

// ---------------- launch ----------------
extern "C" void kernel_launch(void* const* d_in, const int* in_sizes, int n_in,
                              void* d_out, int out_size) {
    const float* x      = (const float*)d_in[0];
    const float* pos    = (const float*)d_in[1];
    const float* cond   = (const float*)d_in[2];
    const float* w_norm = (const float*)d_in[3];
    const float* w_qkv  = (const float*)d_in[4];
    const float* w_out  = (const float*)d_in[5];
    float* out = (float*)d_out;

    k_scale<<<NB, 256>>>(cond, w_norm);
    k_rmsfac<<<TOK / 8, 256>>>(x);

    {
        size_t cs_bytes = 128 * 132 * sizeof(float);   // 67584
        cudaFuncSetAttribute(k_gemm_qkv_rope,
                             cudaFuncAttributeMaxDynamicSharedMemorySize, (int)cs_bytes);
        dim3 g1((3 * DM) / 128, TOK / 128);
        k_gemm_qkv_rope<<<g1, 256, cs_bytes>>>(x, w_qkv, pos);
    }

    {
        size_t sm_bytes = (HALO * KSS + 16 * 64 + 16 * 64) * sizeof(float); // 37760
        cudaFuncSetAttribute(k_attn,
                             cudaFuncAttributeMaxDynamicSharedMemorySize, (int)sm_bytes);
        dim3 g2(WW / 8, HH / 2, NB * NHEAD);
        k_attn<<<g2, 256, sm_bytes>>>();
    }

    {
        float* go; cudaGetSymbolAddress((void**)&go, g_o);
        dim3 g3(DM / 64, TOK / 128);
        k_gemm_out<<<g3, 256>>>(go, w_out, x, out);
    }
}

// round 10
// speedup vs baseline: 1.0840x; 1.0223x over previous
#include <cuda_runtime.h>

#define TOK   4608      // n*H*W
#define NB    2
#define HH    48
#define WW    48
#define DM    256
#define NHEAD 4
#define EH    64
#define EPS   1e-6f

// ---------------- scratch ----------------
__device__ float g_scale[NB * DM];
__device__ float g_rfac [TOK];
__device__ float g_q   [NB * NHEAD * HH * WW * EH];
__device__ float g_k   [NB * NHEAD * HH * WW * EH];
__device__ float g_v   [NB * NHEAD * HH * WW * EH];
__device__ float g_o   [TOK * DM];

// ---------------- packed f32x2 helpers ----------------
__device__ __forceinline__ unsigned long long dupf(float x) {
    unsigned long long r;
    asm("mov.b64 %0,{%1,%2};" : "=l"(r) : "f"(x), "f"(x));
    return r;
}
__device__ __forceinline__ void ffma2(unsigned long long& c, unsigned long long a, unsigned long long b) {
    asm("fma.rn.f32x2 %0,%1,%2,%0;" : "+l"(c) : "l"(a), "l"(b));
}
__device__ __forceinline__ float2 unpk(unsigned long long v) {
    float2 r;
    asm("mov.b64 {%0,%1},%2;" : "=f"(r.x), "=f"(r.y) : "l"(v));
    return r;
}

// ---------------- K0: scale[b][c] = dot(cond[b], w_norm[c]) + 1 ----------------
__global__ void k_scale(const float* __restrict__ cond, const float* __restrict__ w_norm) {
    int b = blockIdx.x, c = threadIdx.x;
    const float4* cv = (const float4*)(cond + b * DM);
    const float4* wv = (const float4*)(w_norm + c * DM);
    float s = 0.f;
#pragma unroll 16
    for (int k = 0; k < DM / 4; k++) {
        float4 a = cv[k], w = wv[k];
        s += a.x * w.x + a.y * w.y + a.z * w.z + a.w * w.w;
    }
    g_scale[b * DM + c] = s + 1.f;
}

// ---------------- K1: per-token rsqrt(mean(x^2)+eps), one warp per token ----------------
__global__ void __launch_bounds__(256) k_rmsfac(const float* __restrict__ x) {
    int warp = threadIdx.x >> 5, lane = threadIdx.x & 31;
    int t = blockIdx.x * 8 + warp;
    const float4* xv = (const float4*)(x + (size_t)t * DM);
    float4 a = xv[lane], b = xv[lane + 32];
    float sq = a.x*a.x + a.y*a.y + a.z*a.z + a.w*a.w
             + b.x*b.x + b.y*b.y + b.z*b.z + b.w*b.w;
#pragma unroll
    for (int o = 16; o > 0; o >>= 1) sq += __shfl_xor_sync(0xffffffffu, sq, o);
    if (lane == 0) g_rfac[t] = rsqrtf(sq * (1.f / DM) + EPS);
}

// ---------------- qkv GEMM (fused rms-norm A-load, FFMA2) + rotary/permute epilogue ----
__global__ void __launch_bounds__(256) k_gemm_qkv_rope(const float* __restrict__ X,
                                                       const float* __restrict__ B,
                                                       const float* __restrict__ pos) {
    constexpr int BM = 128, BK = 16, BN = 128;
    constexpr int K = DM;
    __shared__ float As[2][BK][BM];
    __shared__ float Bs[2][BK][BN];
    extern __shared__ float Cs[];            // [128][132]

    int tid = threadIdx.x;
    int m0 = blockIdx.y * BM, n0 = blockIdx.x * BN;

    int arow = tid >> 1, akh = (tid & 1) * 8;
    int tokA = m0 + arow;
    int bA = tokA / (HH * WW);
    const float* Ag = X + (size_t)tokA * K + akh;
    const float* Sg = g_scale + bA * DM + akh;
    float rfac = g_rfac[tokA];
    const float* Bg = B + (size_t)(n0 + arow) * K + akh;

    float ra[8], rb[8];
    {
        float4 v0 = *(const float4*)(Ag + 0);
        float4 v1 = *(const float4*)(Ag + 4);
        float4 s0 = *(const float4*)(Sg + 0);
        float4 s1 = *(const float4*)(Sg + 4);
        ra[0]=v0.x*s0.x*rfac; ra[1]=v0.y*s0.y*rfac; ra[2]=v0.z*s0.z*rfac; ra[3]=v0.w*s0.w*rfac;
        ra[4]=v1.x*s1.x*rfac; ra[5]=v1.y*s1.y*rfac; ra[6]=v1.z*s1.z*rfac; ra[7]=v1.w*s1.w*rfac;
        float4 w0 = *(const float4*)(Bg + 0);
        float4 w1 = *(const float4*)(Bg + 4);
        rb[0]=w0.x; rb[1]=w0.y; rb[2]=w0.z; rb[3]=w0.w;
        rb[4]=w1.x; rb[5]=w1.y; rb[6]=w1.z; rb[7]=w1.w;
    }
#pragma unroll
    for (int c = 0; c < 8; c++) { As[0][akh + c][arow] = ra[c]; Bs[0][akh + c][arow] = rb[c]; }
    __syncthreads();

    int tx = tid & 15, ty = tid >> 4;
    unsigned long long acc[8][4];
#pragma unroll
    for (int i = 0; i < 8; i++)
#pragma unroll
        for (int j = 0; j < 4; j++) acc[i][j] = 0ull;

    int nkt = K / BK;
    int buf = 0;
    for (int t = 0; t < nkt; t++) {
        if (t + 1 < nkt) {
            int k0 = (t + 1) * BK;
            float4 v0 = *(const float4*)(Ag + k0);
            float4 v1 = *(const float4*)(Ag + k0 + 4);
            float4 s0 = *(const float4*)(Sg + k0);
            float4 s1 = *(const float4*)(Sg + k0 + 4);
            ra[0]=v0.x*s0.x*rfac; ra[1]=v0.y*s0.y*rfac; ra[2]=v0.z*s0.z*rfac; ra[3]=v0.w*s0.w*rfac;
            ra[4]=v1.x*s1.x*rfac; ra[5]=v1.y*s1.y*rfac; ra[6]=v1.z*s1.z*rfac; ra[7]=v1.w*s1.w*rfac;
            float4 w0 = *(const float4*)(Bg + k0);
            float4 w1 = *(const float4*)(Bg + k0 + 4);
            rb[0]=w0.x; rb[1]=w0.y; rb[2]=w0.z; rb[3]=w0.w;
            rb[4]=w1.x; rb[5]=w1.y; rb[6]=w1.z; rb[7]=w1.w;
        }
#pragma unroll
        for (int kk = 0; kk < BK; kk++) {
            float4 a0 = *(const float4*)&As[buf][kk][ty * 8];
            float4 a1 = *(const float4*)&As[buf][kk][ty * 8 + 4];
            ulonglong2 b0 = *(const ulonglong2*)&Bs[buf][kk][tx * 4];
            ulonglong2 b1 = *(const ulonglong2*)&Bs[buf][kk][64 + tx * 4];
            unsigned long long ad[8];
            ad[0]=dupf(a0.x); ad[1]=dupf(a0.y); ad[2]=dupf(a0.z); ad[3]=dupf(a0.w);
            ad[4]=dupf(a1.x); ad[5]=dupf(a1.y); ad[6]=dupf(a1.z); ad[7]=dupf(a1.w);
#pragma unroll
            for (int i = 0; i < 8; i++) {
                ffma2(acc[i][0], ad[i], b0.x);
                ffma2(acc[i][1], ad[i], b0.y);
                ffma2(acc[i][2], ad[i], b1.x);
                ffma2(acc[i][3], ad[i], b1.y);
            }
        }
        if (t + 1 < nkt) {
            int nb = buf ^ 1;
#pragma unroll
            for (int c = 0; c < 8; c++) { As[nb][akh + c][arow] = ra[c]; Bs[nb][akh + c][arow] = rb[c]; }
            __syncthreads();
            buf = nb;
        }
    }

#pragma unroll
    for (int i = 0; i < 8; i++) {
        int r = ty * 8 + i;
        float2 p0 = unpk(acc[i][0]), p1 = unpk(acc[i][1]);
        float2 p2 = unpk(acc[i][2]), p3 = unpk(acc[i][3]);
        *(float4*)&Cs[r * 132 + tx * 4]      = make_float4(p0.x, p0.y, p1.x, p1.y);
        *(float4*)&Cs[r * 132 + 64 + tx * 4] = make_float4(p2.x, p2.y, p3.x, p3.y);
    }
    __syncthreads();

    {
        int r = tid >> 1, half = tid & 1;
        int token = m0 + r;
        int b = token / (HH * WW);
        int ij = token - b * (HH * WW);
        int i = ij / WW, j = ij - i * WW;
        int c_lo = n0 + half * 64;
        int part = c_lo >> 8;            // 0=q 1=k 2=v
        int rem  = c_lo & 255;
        int h = rem >> 6;
        float* dst = (part == 0 ? g_q : part == 1 ? g_k : g_v)
                   + ((size_t)((b * NHEAD + h) * HH + i) * WW + j) * EH;
        const float* src = Cs + r * 132 + half * 64;

        if (part == 2) {
#pragma unroll
            for (int e4 = 0; e4 < 16; e4++)
                *(float4*)(dst + e4 * 4) = *(const float4*)(src + e4 * 4);
        } else {
            float gh = pos[(i * WW + j) * 2 + 0];
            float gw = pos[(i * WW + j) * 2 + 1];
            float fr[8];
#pragma unroll
            for (int fi = 0; fi < 8; fi++)
                fr[fi] = 3.14159265358979323846f * exp10f((float)fi * 0.125f);
            float ov[32];
#pragma unroll
            for (int e = 0; e < 16; e++) {
                float f  = fr[e & 7];
                float p  = (e < 8) ? gh : gw;
                float an = p * f;
                float cs = cosf(an), sn = sinf(an);
                float x1 = src[e], x2 = src[e + 16];
                ov[e]      = x1 * cs - x2 * sn;
                ov[e + 16] = x2 * cs + x1 * sn;
            }
            float sc = (part == 0) ? 0.125f : 1.f;
#pragma unroll
            for (int e4 = 0; e4 < 8; e4++)
                *(float4*)(dst + e4 * 4) = make_float4(ov[e4*4]*sc, ov[e4*4+1]*sc,
                                                       ov[e4*4+2]*sc, ov[e4*4+3]*sc);
#pragma unroll
            for (int e4 = 8; e4 < 16; e4++) {
                float4 v = *(const float4*)(src + e4 * 4);
                *(float4*)(dst + e4 * 4) = make_float4(v.x*sc, v.y*sc, v.z*sc, v.w*sc);
            }
        }
    }
}

// ---------------- plain FFMA2 GEMM for output projection (BN=64) ----------------
__global__ void __launch_bounds__(256) k_gemm_out(const float* __restrict__ A,
                                                  const float* __restrict__ B,
                                                  const float* __restrict__ Sk,
                                                  float* __restrict__ C) {
    constexpr int BK = 16, K = DM, N = DM;
    __shared__ float As[2][BK][128];
    __shared__ float Bs[2][BK][64];

    int tid = threadIdx.x;
    int m0 = blockIdx.y * 128, n0 = blockIdx.x * 64;

    int arow = tid >> 1, akh = (tid & 1) * 8;
    int brow = tid >> 2, bkh = (tid & 3) * 4;
    const float* Ag = A + (size_t)(m0 + arow) * K + akh;
    const float* Bg = B + (size_t)(n0 + brow) * K + bkh;

    float ra[8], rb[4];
    {
        float4 v0 = *(const float4*)(Ag + 0);
        float4 v1 = *(const float4*)(Ag + 4);
        ra[0]=v0.x; ra[1]=v0.y; ra[2]=v0.z; ra[3]=v0.w;
        ra[4]=v1.x; ra[5]=v1.y; ra[6]=v1.z; ra[7]=v1.w;
        float4 w0 = *(const float4*)(Bg + 0);
        rb[0]=w0.x; rb[1]=w0.y; rb[2]=w0.z; rb[3]=w0.w;
    }
#pragma unroll
    for (int c = 0; c < 8; c++) As[0][akh + c][arow] = ra[c];
#pragma unroll
    for (int c = 0; c < 4; c++) Bs[0][bkh + c][brow] = rb[c];
    __syncthreads();

    int tx = tid & 15, ty = tid >> 4;
    unsigned long long acc[8][2];
#pragma unroll
    for (int i = 0; i < 8; i++) { acc[i][0] = 0ull; acc[i][1] = 0ull; }

    int nkt = K / BK;
    int buf = 0;
    for (int t = 0; t < nkt; t++) {
        if (t + 1 < nkt) {
            int k0 = (t + 1) * BK;
            float4 v0 = *(const float4*)(Ag + k0);
            float4 v1 = *(const float4*)(Ag + k0 + 4);
            ra[0]=v0.x; ra[1]=v0.y; ra[2]=v0.z; ra[3]=v0.w;
            ra[4]=v1.x; ra[5]=v1.y; ra[6]=v1.z; ra[7]=v1.w;
            float4 w0 = *(const float4*)(Bg + k0);
            rb[0]=w0.x; rb[1]=w0.y; rb[2]=w0.z; rb[3]=w0.w;
        }
#pragma unroll
        for (int kk = 0; kk < BK; kk++) {
            float4 a0 = *(const float4*)&As[buf][kk][ty * 8];
            float4 a1 = *(const float4*)&As[buf][kk][ty * 8 + 4];
            ulonglong2 b0 = *(const ulonglong2*)&Bs[buf][kk][tx * 4];
            unsigned long long ad[8];
            ad[0]=dupf(a0.x); ad[1]=dupf(a0.y); ad[2]=dupf(a0.z); ad[3]=dupf(a0.w);
            ad[4]=dupf(a1.x); ad[5]=dupf(a1.y); ad[6]=dupf(a1.z); ad[7]=dupf(a1.w);
#pragma unroll
            for (int i = 0; i < 8; i++) {
                ffma2(acc[i][0], ad[i], b0.x);
                ffma2(acc[i][1], ad[i], b0.y);
            }
        }
        if (t + 1 < nkt) {
            int nb = buf ^ 1;
#pragma unroll
            for (int c = 0; c < 8; c++) As[nb][akh + c][arow] = ra[c];
#pragma unroll
            for (int c = 0; c < 4; c++) Bs[nb][bkh + c][brow] = rb[c];
            __syncthreads();
            buf = nb;
        }
    }

#pragma unroll
    for (int i = 0; i < 8; i++) {
        int m = m0 + ty * 8 + i, nn = n0 + tx * 4;
        float2 p0 = unpk(acc[i][0]), p1 = unpk(acc[i][1]);
        float4 s = *(const float4*)&Sk[(size_t)m * N + nn];
        *(float4*)&C[(size_t)m * N + nn] =
            make_float4(p0.x + s.x, p0.y + s.y, p1.x + s.z, p1.y + s.w);
    }
}

// ---------------- attention v3: LDS.128 QK (stride 68), const-addr AV ----------------
#define KSS  68            // 272B rows: 16B-aligned, conflict-free LDS.128 phases
#define ASS  52
#define HALO 112           // 8 rows x 14 cols
__global__ void __launch_bounds__(256) k_attn() {
    extern __shared__ float sm[];
    float* ks  = sm;                       // [112][68]
    float* qs  = sm + HALO * KSS;          // [16][64]
    float* as_ = qs + 16 * 64;             // [16][52] (50 used: 49 probs + zero pad)

    int j0 = blockIdx.x * 8;
    int i0 = blockIdx.y * 2;
    int bh = blockIdx.z;
    int b = bh >> 2, h = bh & 3;
    int tid = threadIdx.x;
    int warp = tid >> 5, lane = tid & 31;

    int r0 = min(max(i0 - 3, 0), HH - 8);
    int c0 = min(max(j0 - 3, 0), WW - 14);

    const float* kg = g_k + (size_t)(b * NHEAD + h) * HH * WW * EH;
    const float* vg = g_v + (size_t)(b * NHEAD + h) * HH * WW * EH;
    const float* qg = g_q + (size_t)(b * NHEAD + h) * HH * WW * EH;

    // K halo: float4 both sides (row base 272B = 16B-aligned)
    for (int idx = tid; idx < HALO * 16; idx += 256) {
        int p = idx >> 4, c4 = idx & 15;
        int r = r0 + p / 14, c = c0 + p % 14;
        *(float4*)(ks + p * KSS + c4 * 4) =
            *(const float4*)(kg + ((size_t)r * WW + c) * EH + c4 * 4);
    }
    for (int idx = tid; idx < 16 * 16; idx += 256) {
        int qi = idx >> 4, c4 = idx & 15;
        int iq = i0 + (qi >> 3), jq = j0 + (qi & 7);
        *(float4*)(qs + qi * 64 + c4 * 4) =
            *(const float4*)(qg + ((size_t)iq * WW + jq) * EH + c4 * 4);
    }
    __syncthreads();

#pragma unroll
    for (int s = 0; s < 2; s++) {
        int qi = warp * 2 + s;
        int di = qi >> 3, dj = qi & 7;
        int iq = i0 + di, jq = j0 + dj;
        int sh = min(max(iq - 3, 0), HH - 7);
        int sw = min(max(jq - 3, 0), WW - 7);
        int offq = (sh - r0) * 14 + (sw - c0);

        // QK: lane owns positions pA=lane, pB=lane+32 (clamped; lanes>=17 discarded)
        int pA = lane;
        int pB = min(lane + 32, 48);
        const float* kA = ks + (offq + (pA / 7) * 14 + pA % 7) * KSS;
        const float* kB = ks + (offq + (pB / 7) * 14 + pB % 7) * KSS;
        const float* qrow = qs + qi * 64;
        unsigned long long a0 = 0ull, a1 = 0ull, b0 = 0ull, b1 = 0ull;
#pragma unroll
        for (int e = 0; e < 64; e += 4) {
            ulonglong2 qp = *(const ulonglong2*)(qrow + e);
            ulonglong2 ka = *(const ulonglong2*)(kA + e);
            ulonglong2 kb = *(const ulonglong2*)(kB + e);
            ffma2(a0, qp.x, ka.x); ffma2(a1, qp.y, ka.y);
            ffma2(b0, qp.x, kb.x); ffma2(b1, qp.y, kb.y);
        }
        float2 uA0 = unpk(a0), uA1 = unpk(a1);
        float2 uB0 = unpk(b0), uB1 = unpk(b1);
        float sA = (uA0.x + uA0.y) + (uA1.x + uA1.y);
        float sB = (lane < 17) ? (uB0.x + uB0.y) + (uB1.x + uB1.y) : -1e30f;

        float mx = fmaxf(sA, sB);
#pragma unroll
        for (int o = 16; o > 0; o >>= 1) mx = fmaxf(mx, __shfl_xor_sync(0xffffffffu, mx, o));
        float eA = __expf(sA - mx);
        float eB = (lane < 17) ? __expf(sB - mx) : 0.f;
        float sum = eA + eB;
#pragma unroll
        for (int o = 16; o > 0; o >>= 1) sum += __shfl_xor_sync(0xffffffffu, sum, o);
        float inv = 1.f / sum;

        as_[qi * ASS + lane] = eA * inv;
        if (lane < 18) as_[qi * ASS + 32 + lane] = eB * inv;   // lane17 writes 0 pad
        __syncwarp();

        // AV: V from gmem with compile-time offsets (unrolled), 2 ch per lane
        unsigned long long acc = 0ull;
        const float* vbase = vg + ((size_t)sh * WW + sw) * EH + 2 * lane;
        const float* arow  = as_ + qi * ASS;
#pragma unroll
        for (int p = 0; p < 49; p++) {
            float a = arow[p];
            ffma2(acc, dupf(a),
                  *(const unsigned long long*)(vbase + ((p / 7) * WW + (p % 7)) * EH));
        }
        float2 r = unpk(acc);
        int tok = b * (HH * WW) + iq * WW + jq;
        *(float2*)(g_o + (size_t)tok * DM + h * EH + 2 * lane) = r;
        __syncwarp();
    }
}

// ---------------- launch ----------------
extern "C" void kernel_launch(void* const* d_in, const int* in_sizes, int n_in,
                              void* d_out, int out_size) {
    const float* x      = (const float*)d_in[0];
    const float* pos    = (const float*)d_in[1];
    const float* cond   = (const float*)d_in[2];
    const float* w_norm = (const float*)d_in[3];
    const float* w_qkv  = (const float*)d_in[4];
    const float* w_out  = (const float*)d_in[5];
    float* out = (float*)d_out;

    k_scale<<<NB, 256>>>(cond, w_norm);
    k_rmsfac<<<TOK / 8, 256>>>(x);

    {
        size_t cs_bytes = 128 * 132 * sizeof(float);   // 67584
        cudaFuncSetAttribute(k_gemm_qkv_rope,
                             cudaFuncAttributeMaxDynamicSharedMemorySize, (int)cs_bytes);
        dim3 g1((3 * DM) / 128, TOK / 128);
        k_gemm_qkv_rope<<<g1, 256, cs_bytes>>>(x, w_qkv, pos);
    }

    {
        size_t sm_bytes = (HALO * KSS + 16 * 64 + 16 * ASS) * sizeof(float); // 37888
        cudaFuncSetAttribute(k_attn,
                             cudaFuncAttributeMaxDynamicSharedMemorySize, (int)sm_bytes);
        dim3 g2(WW / 8, HH / 2, NB * NHEAD);
        k_attn<<<g2, 256, sm_bytes>>>();
    }

    {
        float* go; cudaGetSymbolAddress((void**)&go, g_o);
        dim3 g3(DM / 64, TOK / 128);
        k_gemm_out<<<g3, 256>>>(go, w_out, x, out);
    }
}